// round 1
// baseline (speedup 1.0000x reference)
#include <cuda_runtime.h>
#include <cuda_bf16.h>
#include <cstdint>

// Problem constants
#define NQ 8100      // query patches (90*90)
#define NK 8100      // key rows
#define D  147       // 3*7*7
#define DP 148       // padded depth (pad=0)
#define HO 90
#define H  96

// GEMM tile config
#define BM 56        // query rows per block -> ceil(8100/56)=145 blocks (~1 wave on 148 SMs)
#define BN 128       // key cols per chunk
#define NTHREADS 224 // ty in [0,14) x tx in [0,16); micro-tile 4 rows x 8 cols
#define NCHUNK 64    // ceil(8100/128)

// -------- device scratch (no allocations allowed) --------
__device__ float g_q2dT[DP * NQ];   // d-major unfolded query
__device__ float g_keyT[DP * NK];   // d-major key
__device__ float g_kn[NK];          // ||k||^2
__device__ int   g_idx[NQ];         // argmin result

// -------- f32x2 packed math helpers (Blackwell FFMA2) --------
__device__ __forceinline__ unsigned long long pack2(float x, float y) {
    unsigned long long r;
    asm("mov.b64 %0, {%1, %2};" : "=l"(r) : "f"(x), "f"(y));
    return r;
}
__device__ __forceinline__ void fma2(unsigned long long& acc,
                                     unsigned long long a,
                                     unsigned long long b) {
    asm("fma.rn.f32x2 %0, %1, %2, %0;" : "+l"(acc) : "l"(a), "l"(b));
}
__device__ __forceinline__ void unpack2(unsigned long long v, float& lo, float& hi) {
    asm("mov.b64 {%0, %1}, %2;" : "=f"(lo), "=f"(hi) : "l"(v));
}

// -------- prep: transpose key into d-major, zero-pad d=147 --------
__global__ void prep_key_kernel(const float* __restrict__ key) {
    int t = blockIdx.x * blockDim.x + threadIdx.x;
    if (t >= DP * NK) return;
    int d = t / NK;
    int k = t - d * NK;
    g_keyT[t] = (d < D) ? key[k * D + d] : 0.0f;
}

// -------- prep: ||k||^2 per row (one warp per row) --------
__global__ void prep_kn_kernel(const float* __restrict__ key) {
    int row  = blockIdx.x * 8 + (threadIdx.x >> 5);
    int lane = threadIdx.x & 31;
    if (row >= NK) return;
    float s = 0.0f;
    for (int d = lane; d < D; d += 32) {
        float v = key[row * D + d];
        s = fmaf(v, v, s);
    }
    #pragma unroll
    for (int off = 16; off > 0; off >>= 1)
        s += __shfl_down_sync(0xffffffffu, s, off);
    if (lane == 0) g_kn[row] = s;
}

// -------- prep: unfold query into d-major q2dT, zero-pad d=147 --------
__global__ void prep_q_kernel(const float* __restrict__ query) {
    int t = blockIdx.x * blockDim.x + threadIdx.x;
    if (t >= DP * NQ) return;
    int d = t / NQ;
    int p = t - d * NQ;
    float v = 0.0f;
    if (d < D) {
        int c  = d / 49;
        int rr = d - c * 49;
        int i  = rr / 7;
        int j  = rr - i * 7;
        int pi = p / HO;
        int pj = p - pi * HO;
        v = query[c * (H * H) + (pi + i) * H + (pj + j)];
    }
    g_q2dT[t] = v;
}

// -------- main: distance argmin GEMM --------
// score(q,k) = ||k||^2 - 2 q.k  (||q||^2 constant per row -> dropped)
__global__ __launch_bounds__(NTHREADS, 1)
void nn_argmin_kernel() {
    extern __shared__ float sm[];
    float* Qs  = sm;                    // DP * BM  = 8288
    float* Ks  = sm + DP * BM;          // DP * BN  = 18944
    float* kns = sm + DP * BM + DP * BN;// BN       = 128

    const int tid = threadIdx.x;
    const int tx  = tid & 15;   // 16 col groups of 8
    const int ty  = tid >> 4;   // 14 row groups of 4
    const int rowBase = blockIdx.x * BM;

    // Load this block's Q tile once (d-major, stride BM in smem)
    for (int t = tid; t < DP * BM; t += NTHREADS) {
        int d = t / BM;
        int r = t - d * BM;
        int row = rowBase + r;
        Qs[t] = (row < NQ) ? g_q2dT[d * NQ + row] : 0.0f;
    }

    float best[4];
    int   bidx[4];
    #pragma unroll
    for (int r = 0; r < 4; ++r) { best[r] = 3.402823466e38f; bidx[r] = 0x7fffffff; }

    for (int ck = 0; ck < NCHUNK; ++ck) {
        const int col0 = ck * BN;
        __syncthreads();   // protect Ks/kns readers of previous chunk
        // Load key chunk (d-major) + kn
        for (int t = tid; t < DP * BN; t += NTHREADS) {
            int d = t / BN;
            int c = t - d * BN;
            int col = col0 + c;
            Ks[t] = (col < NK) ? g_keyT[d * NK + col] : 0.0f;
        }
        if (tid < BN) {
            int col = col0 + tid;
            kns[tid] = (col < NK) ? g_kn[col] : 3.402823466e38f;
        }
        __syncthreads();

        unsigned long long acc[4][4];
        #pragma unroll
        for (int r = 0; r < 4; ++r)
            #pragma unroll
            for (int c = 0; c < 4; ++c) acc[r][c] = 0ull;

        const float* qp = Qs + (ty << 2);
        const float* kp = Ks + (tx << 3);
        #pragma unroll 4
        for (int d = 0; d < DP; ++d) {
            float4 a = *reinterpret_cast<const float4*>(qp + d * BM);
            longlong2 b0 = *reinterpret_cast<const longlong2*>(kp + d * BN);
            longlong2 b1 = *reinterpret_cast<const longlong2*>(kp + d * BN + 4);
            unsigned long long bb0 = (unsigned long long)b0.x;
            unsigned long long bb1 = (unsigned long long)b0.y;
            unsigned long long bb2 = (unsigned long long)b1.x;
            unsigned long long bb3 = (unsigned long long)b1.y;
            unsigned long long aa;
            aa = pack2(a.x, a.x);
            fma2(acc[0][0], aa, bb0); fma2(acc[0][1], aa, bb1);
            fma2(acc[0][2], aa, bb2); fma2(acc[0][3], aa, bb3);
            aa = pack2(a.y, a.y);
            fma2(acc[1][0], aa, bb0); fma2(acc[1][1], aa, bb1);
            fma2(acc[1][2], aa, bb2); fma2(acc[1][3], aa, bb3);
            aa = pack2(a.z, a.z);
            fma2(acc[2][0], aa, bb0); fma2(acc[2][1], aa, bb1);
            fma2(acc[2][2], aa, bb2); fma2(acc[2][3], aa, bb3);
            aa = pack2(a.w, a.w);
            fma2(acc[3][0], aa, bb0); fma2(acc[3][1], aa, bb1);
            fma2(acc[3][2], aa, bb2); fma2(acc[3][3], aa, bb3);
        }

        // Score & argmin (ascending col order -> strict < keeps first min)
        #pragma unroll
        for (int r = 0; r < 4; ++r) {
            #pragma unroll
            for (int c2 = 0; c2 < 4; ++c2) {
                float lo, hi;
                unpack2(acc[r][c2], lo, hi);
                int c  = (tx << 3) + (c2 << 1);
                float s0 = fmaf(-2.0f, lo, kns[c]);
                float s1 = fmaf(-2.0f, hi, kns[c + 1]);
                int j0 = col0 + c;
                if (s0 < best[r]) { best[r] = s0; bidx[r] = j0; }
                if (s1 < best[r]) { best[r] = s1; bidx[r] = j0 + 1; }
            }
        }
    }

    // Reduce across the 16 tx lanes that share each query row (width-16 shfl)
    #pragma unroll
    for (int r = 0; r < 4; ++r) {
        float b = best[r];
        int   i = bidx[r];
        #pragma unroll
        for (int off = 8; off > 0; off >>= 1) {
            float ob = __shfl_down_sync(0xffffffffu, b, off, 16);
            int   oi = __shfl_down_sync(0xffffffffu, i, off, 16);
            if (ob < b || (ob == b && oi < i)) { b = ob; i = oi; }
        }
        if (tx == 0) {
            int row = rowBase + (ty << 2) + r;
            if (row < NQ) g_idx[row] = i;
        }
    }
}

// -------- fold: gather matched value patches, overlap-add mean --------
__global__ void fold_kernel(const float* __restrict__ value, float* __restrict__ out) {
    int pix = blockIdx.x * blockDim.x + threadIdx.x;
    if (pix >= H * H) return;
    int y = pix / H, x = pix - y * H;
    int pi0 = max(0, y - 6), pi1 = min(HO - 1, y);
    int pj0 = max(0, x - 6), pj1 = min(HO - 1, x);
    float s0 = 0.0f, s1 = 0.0f, s2 = 0.0f;
    for (int pi = pi0; pi <= pi1; ++pi) {
        int di = y - pi;
        for (int pj = pj0; pj <= pj1; ++pj) {
            int row  = g_idx[pi * HO + pj];
            int base = row * D + di * 7 + (x - pj);
            s0 += __ldg(value + base);
            s1 += __ldg(value + base + 49);
            s2 += __ldg(value + base + 98);
        }
    }
    float inv = 1.0f / (float)((pi1 - pi0 + 1) * (pj1 - pj0 + 1));
    out[pix]             = s0 * inv;
    out[H * H + pix]     = s1 * inv;
    out[2 * H * H + pix] = s2 * inv;
}

extern "C" void kernel_launch(void* const* d_in, const int* in_sizes, int n_in,
                              void* d_out, int out_size) {
    const float* query = (const float*)d_in[0];  // [1,3,96,96]
    const float* key   = (const float*)d_in[1];  // [8100,147]
    const float* value = (const float*)d_in[2];  // [8100,147]
    float* out = (float*)d_out;                  // [1,3,96,96]

    // Prep
    {
        int n = DP * NK;
        prep_key_kernel<<<(n + 255) / 256, 256>>>(key);
        prep_kn_kernel<<<(NK + 7) / 8, 256>>>(key);
        int nq = DP * NQ;
        prep_q_kernel<<<(nq + 255) / 256, 256>>>(query);
    }

    // Argmin GEMM
    {
        size_t smem = (size_t)(DP * BM + DP * BN + BN) * sizeof(float); // 109,440 B
        cudaFuncSetAttribute(nn_argmin_kernel,
                             cudaFuncAttributeMaxDynamicSharedMemorySize, (int)smem);
        int grid = (NQ + BM - 1) / BM;  // 145
        nn_argmin_kernel<<<grid, NTHREADS, smem>>>();
    }

    // Fold
    {
        int n = H * H;
        fold_kernel<<<(n + 127) / 128, 128>>>(value, out);
    }
}

// round 2
// speedup vs baseline: 1.6867x; 1.6867x over previous
#include <cuda_runtime.h>
#include <cuda_bf16.h>
#include <cstdint>

typedef unsigned long long ull;

// Problem constants
#define NQ 8100
#define NK 8100
#define D  147
#define DP 148
#define HO 90
#define H  96

#define NKP 8192          // padded key cols (power of 2)
#define NQP 8120          // padded query rows (145*56)

// GEMM tile config
#define BM 56             // 145 row-blocks
#define BN 128
#define NTHREADS 224      // ty 14 x tx 16, micro-tile 4x8
#define SPLITK 2          // grid = 145 x 2 = 290 ~= 2 CTAs/SM
#define CHUNKS_PER_SPLIT 32   // 32*128 = 4096 cols per split

// -------- device scratch --------
__device__ float g_q2dT[DP * NQP];
__device__ float g_keyT[DP * NKP];
__device__ float g_kn[NKP];
__device__ ull   g_cand[NQ];     // packed (orderable score << 32) | idx

// -------- f32x2 helpers --------
__device__ __forceinline__ ull pack2(float x, float y) {
    ull r; asm("mov.b64 %0, {%1, %2};" : "=l"(r) : "f"(x), "f"(y)); return r;
}
__device__ __forceinline__ void fma2(ull& acc, ull a, ull b) {
    asm("fma.rn.f32x2 %0, %1, %2, %0;" : "+l"(acc) : "l"(a), "l"(b));
}
__device__ __forceinline__ void unpack2(ull v, float& lo, float& hi) {
    asm("mov.b64 {%0, %1}, %2;" : "=f"(lo), "=f"(hi) : "l"(v));
}
__device__ __forceinline__ unsigned fkey(float f) {
    unsigned u = __float_as_uint(f);
    return (u & 0x80000000u) ? ~u : (u | 0x80000000u);
}

// -------- prep kernels --------
__global__ void prep_key_kernel(const float* __restrict__ key) {
    int t = blockIdx.x * blockDim.x + threadIdx.x;
    if (t >= DP * NKP) return;
    int d = t >> 13;           // /8192
    int k = t & (NKP - 1);
    g_keyT[t] = (d < D && k < NK) ? key[k * D + d] : 0.0f;
}

__global__ void prep_kn_kernel(const float* __restrict__ key) {
    int row  = blockIdx.x * 8 + (threadIdx.x >> 5);
    int lane = threadIdx.x & 31;
    if (row >= NKP) return;
    if (row >= NK) { if (lane == 0) g_kn[row] = __int_as_float(0x7f800000); return; }
    float s = 0.0f;
    for (int d = lane; d < D; d += 32) {
        float v = key[row * D + d];
        s = fmaf(v, v, s);
    }
    #pragma unroll
    for (int off = 16; off > 0; off >>= 1)
        s += __shfl_down_sync(0xffffffffu, s, off);
    if (lane == 0) g_kn[row] = s;
}

__global__ void prep_q_kernel(const float* __restrict__ query) {
    int t = blockIdx.x * blockDim.x + threadIdx.x;
    if (t >= DP * NQP) return;
    int d = t / NQP;
    int p = t - d * NQP;
    float v = 0.0f;
    if (d < D && p < NQ) {
        int c  = d / 49;
        int rr = d - c * 49;
        int i  = rr / 7;
        int j  = rr - i * 7;
        int pi = p / HO;
        int pj = p - pi * HO;
        v = query[c * (H * H) + (pi + i) * H + (pj + j)];
    }
    g_q2dT[t] = v;
}

__global__ void init_cand_kernel() {
    int t = blockIdx.x * blockDim.x + threadIdx.x;
    if (t < NQ) g_cand[t] = 0xFFFFFFFFFFFFFFFFull;
}

// -------- main: distance argmin GEMM (split-K, diagonal f32x2 pairing) --------
// score(q,k) = ||k||^2 - 2 q.k
__global__ __launch_bounds__(NTHREADS, 2)
void nn_argmin_kernel() {
    extern __shared__ float sm[];
    float* Qs  = sm;                         // DP*BM
    float* Ks  = sm + DP * BM;               // DP*BN
    float* kns = sm + DP * BM + DP * BN;     // BN

    const int tid = threadIdx.x;
    const int tx  = tid & 15;       // 16 col groups: cols 4tx..4tx+3 and 64+4tx..
    const int ty  = tid >> 4;       // 14 row groups of 4
    const int rowBase = blockIdx.x * BM;
    const int split   = blockIdx.y;
    const int colBase = split * (CHUNKS_PER_SPLIT * BN);

    // Load this block's Q tile once (d-major, natural rows)
    for (int t = tid; t < DP * BM; t += NTHREADS) {
        int d = t / BM;
        int r = t - d * BM;
        Qs[t] = g_q2dT[d * NQP + rowBase + r];   // rowBase+r < NQP always
    }

    float best[4];
    int   bidx[4];
    #pragma unroll
    for (int r = 0; r < 4; ++r) { best[r] = 3.402823466e38f; bidx[r] = 0; }

    for (int ck = 0; ck < CHUNKS_PER_SPLIT; ++ck) {
        const int col0 = colBase + ck * BN;
        __syncthreads();   // protect Ks/kns of previous chunk
        // Load key chunk (d-major), guard-free thanks to NKP padding
        {
            const float4* src = reinterpret_cast<const float4*>(g_keyT);
            float4* dst = reinterpret_cast<float4*>(Ks);
            // DP*BN/4 = 4736 float4s
            for (int t = tid; t < DP * (BN / 4); t += NTHREADS) {
                int d = t >> 5;            // /(BN/4)=32
                int c4 = t & 31;
                dst[t] = src[(d * NKP + col0) / 4 + c4];
            }
            if (tid < BN) kns[tid] = g_kn[col0 + tid];
        }
        __syncthreads();

        ull acc[4][4];
        #pragma unroll
        for (int p = 0; p < 4; ++p)
            #pragma unroll
            for (int j = 0; j < 4; ++j) acc[p][j] = 0ull;

        const float* qp = Qs + (ty << 2);
        const float* kp = Ks + (tx << 2);
        #pragma unroll 2
        for (int d = 0; d < DP; ++d) {
            float4 a = *reinterpret_cast<const float4*>(qp + d * BM);
            longlong2 b0 = *reinterpret_cast<const longlong2*>(kp + d * BN);       // cols 4tx..+3
            longlong2 b1 = *reinterpret_cast<const longlong2*>(kp + d * BN + 64);  // cols 64+4tx..+3
            ull B0 = (ull)b0.x, B1 = (ull)b0.y, B2 = (ull)b1.x, B3 = (ull)b1.y;
            ull A0  = pack2(a.x, a.y);   // natural pair (rows 0,1)
            ull A0s = pack2(a.y, a.x);   // swapped
            ull A1  = pack2(a.z, a.w);   // natural pair (rows 2,3)
            ull A1s = pack2(a.w, a.z);
            fma2(acc[0][0], A0,  B0); fma2(acc[0][1], A0,  B1);
            fma2(acc[0][2], A0,  B2); fma2(acc[0][3], A0,  B3);
            fma2(acc[1][0], A0s, B0); fma2(acc[1][1], A0s, B1);
            fma2(acc[1][2], A0s, B2); fma2(acc[1][3], A0s, B3);
            fma2(acc[2][0], A1,  B0); fma2(acc[2][1], A1,  B1);
            fma2(acc[2][2], A1,  B2); fma2(acc[2][3], A1,  B3);
            fma2(acc[3][0], A1s, B0); fma2(acc[3][1], A1s, B1);
            fma2(acc[3][2], A1s, B2); fma2(acc[3][3], A1s, B3);
        }

        // Decode diagonal pairs & update running argmin (ascending col order)
        // acc[2P][j]   = (row0*ceven, row1*codd)   rows = 4ty+2P+{0,1}
        // acc[2P+1][j] = (row1*ceven, row0*codd)
        #pragma unroll
        for (int P = 0; P < 2; ++P) {
            #pragma unroll
            for (int j = 0; j < 4; ++j) {
                int cl = (tx << 2) + ((j & 1) << 1) + ((j >> 1) << 6);
                float nlo, nhi, slo, shi;
                unpack2(acc[2 * P][j],     nlo, nhi);
                unpack2(acc[2 * P + 1][j], slo, shi);
                float k0 = kns[cl], k1 = kns[cl + 1];
                int c0 = col0 + cl;
                float se0 = fmaf(-2.0f, nlo, k0);   // (row0, ceven)
                float so0 = fmaf(-2.0f, shi, k1);   // (row0, codd)
                float se1 = fmaf(-2.0f, slo, k0);   // (row1, ceven)
                float so1 = fmaf(-2.0f, nhi, k1);   // (row1, codd)
                int r0 = 2 * P, r1 = 2 * P + 1;
                if (se0 < best[r0]) { best[r0] = se0; bidx[r0] = c0; }
                if (so0 < best[r0]) { best[r0] = so0; bidx[r0] = c0 + 1; }
                if (se1 < best[r1]) { best[r1] = se1; bidx[r1] = c0; }
                if (so1 < best[r1]) { best[r1] = so1; bidx[r1] = c0 + 1; }
            }
        }
    }

    // Reduce across 16 tx lanes sharing each query row, then atomic merge
    #pragma unroll
    for (int rr = 0; rr < 4; ++rr) {
        float b = best[rr];
        int   i = bidx[rr];
        #pragma unroll
        for (int off = 8; off > 0; off >>= 1) {
            float ob = __shfl_down_sync(0xffffffffu, b, off, 16);
            int   oi = __shfl_down_sync(0xffffffffu, i, off, 16);
            if (ob < b || (ob == b && oi < i)) { b = ob; i = oi; }
        }
        if (tx == 0) {
            int row = rowBase + (ty << 2) + rr;
            if (row < NQ)
                atomicMin(&g_cand[row], (((ull)fkey(b)) << 32) | (unsigned)i);
        }
    }
}

// -------- fold: gather matched value patches, overlap-add mean --------
__global__ void fold_kernel(const float* __restrict__ value, float* __restrict__ out) {
    int pix = blockIdx.x * blockDim.x + threadIdx.x;
    if (pix >= H * H) return;
    int y = pix / H, x = pix - y * H;
    int pi0 = max(0, y - 6), pi1 = min(HO - 1, y);
    int pj0 = max(0, x - 6), pj1 = min(HO - 1, x);
    float s0 = 0.0f, s1 = 0.0f, s2 = 0.0f;
    for (int pi = pi0; pi <= pi1; ++pi) {
        int di = y - pi;
        for (int pj = pj0; pj <= pj1; ++pj) {
            int row  = (int)(unsigned)(g_cand[pi * HO + pj] & 0xffffffffull);
            int base = row * D + di * 7 + (x - pj);
            s0 += __ldg(value + base);
            s1 += __ldg(value + base + 49);
            s2 += __ldg(value + base + 98);
        }
    }
    float inv = 1.0f / (float)((pi1 - pi0 + 1) * (pj1 - pj0 + 1));
    out[pix]             = s0 * inv;
    out[H * H + pix]     = s1 * inv;
    out[2 * H * H + pix] = s2 * inv;
}

extern "C" void kernel_launch(void* const* d_in, const int* in_sizes, int n_in,
                              void* d_out, int out_size) {
    const float* query = (const float*)d_in[0];
    const float* key   = (const float*)d_in[1];
    const float* value = (const float*)d_in[2];
    float* out = (float*)d_out;

    {
        int n = DP * NKP;
        prep_key_kernel<<<(n + 255) / 256, 256>>>(key);
        prep_kn_kernel<<<NKP / 8, 256>>>(key);
        int nq = DP * NQP;
        prep_q_kernel<<<(nq + 255) / 256, 256>>>(query);
        init_cand_kernel<<<(NQ + 255) / 256, 256>>>();
    }

    {
        size_t smem = (size_t)(DP * BM + DP * BN + BN) * sizeof(float); // 109,440 B
        cudaFuncSetAttribute(nn_argmin_kernel,
                             cudaFuncAttributeMaxDynamicSharedMemorySize, (int)smem);
        dim3 grid((NQ + BM - 1) / BM, SPLITK);  // 145 x 2
        nn_argmin_kernel<<<grid, NTHREADS, smem>>>();
    }

    {
        int n = H * H;
        fold_kernel<<<(n + 127) / 128, 128>>>(value, out);
    }
}

// round 4
// speedup vs baseline: 3.4448x; 2.0423x over previous
#include <cuda_runtime.h>
#include <cstdint>

typedef unsigned long long ull;

// ---------------- problem constants ----------------
#define NQ 8100
#define NK 8100
#define D_ 147
#define HO 90
#define H  96

#define KTERM 160          // per-term K (147 -> 160)
#define KT    480          // expanded K: [big | small | big] vs [big | big | small]
#define NR    8192         // padded rows
#define BM    128
#define BN    128
#define BK    32
#define KTILES 15          // 480/32

// ---------------- device scratch ----------------
__device__ __align__(256) float g_A[(size_t)NR * KT];   // [qb | qs | qb]
__device__ __align__(256) float g_B[(size_t)NR * KT];   // [kb | kb | ks]
__device__ float g_kn[NR];
__device__ ull   g_cand[NR];

// ---------------- helpers ----------------
__device__ __forceinline__ uint32_t smem_u32(const void* p) {
    uint32_t a;
    asm("{ .reg .u64 t; cvta.to.shared.u64 t, %1; cvt.u32.u64 %0, t; }" : "=r"(a) : "l"(p));
    return a;
}
__device__ __forceinline__ unsigned fkey(float f) {
    unsigned u = __float_as_uint(f);
    return (u & 0x80000000u) ? ~u : (u | 0x80000000u);
}
__device__ __forceinline__ void cp16(uint32_t dst, const void* src) {
    asm volatile("cp.async.cg.shared.global [%0], [%1], 16;" :: "r"(dst), "l"(src));
}
__device__ __forceinline__ void ldmatrix_x4(uint32_t* r, uint32_t addr) {
    asm volatile("ldmatrix.sync.aligned.m8n8.x4.shared.b16 {%0,%1,%2,%3}, [%4];"
                 : "=r"(r[0]), "=r"(r[1]), "=r"(r[2]), "=r"(r[3]) : "r"(addr));
}
__device__ __forceinline__ void mma_tf32(float* c, const uint32_t* a, uint32_t b0, uint32_t b1) {
    asm volatile(
        "mma.sync.aligned.m16n8k8.row.col.f32.tf32.tf32.f32 "
        "{%0,%1,%2,%3}, {%4,%5,%6,%7}, {%8,%9}, {%0,%1,%2,%3};"
        : "+f"(c[0]), "+f"(c[1]), "+f"(c[2]), "+f"(c[3])
        : "r"(a[0]), "r"(a[1]), "r"(a[2]), "r"(a[3]), "r"(b0), "r"(b1));
}
__device__ __forceinline__ float tf32_rna(float x) {
    uint32_t u; asm("cvt.rna.tf32.f32 %0, %1;" : "=r"(u) : "f"(x));
    return __uint_as_float(u);
}

// ---------------- prep kernels ----------------
__global__ void prep_A_kernel(const float* __restrict__ query) {
    int t = blockIdx.x * 256 + threadIdx.x;
    if (t >= NR * KTERM) return;
    int p = t / KTERM, k = t - p * KTERM;
    float x = 0.0f;
    if (p < NQ && k < D_) {
        int c  = k / 49;
        int rr = k - c * 49;
        int i  = rr / 7;
        int j  = rr - i * 7;
        int pi = p / HO;
        int pj = p - pi * HO;
        x = query[c * (H * H) + (pi + i) * H + (pj + j)];
    }
    float big = tf32_rna(x);
    float sml = tf32_rna(x - big);
    size_t row = (size_t)p * KT;
    g_A[row + k]             = big;
    g_A[row + KTERM + k]     = sml;
    g_A[row + 2 * KTERM + k] = big;
}

__global__ void prep_B_kernel(const float* __restrict__ key) {
    int t = blockIdx.x * 256 + threadIdx.x;
    if (t >= NR * KTERM) return;
    int p = t / KTERM, k = t - p * KTERM;
    float x = (p < NK && k < D_) ? key[p * D_ + k] : 0.0f;
    float big = tf32_rna(x);
    float sml = tf32_rna(x - big);
    size_t row = (size_t)p * KT;
    g_B[row + k]             = big;
    g_B[row + KTERM + k]     = big;
    g_B[row + 2 * KTERM + k] = sml;
}

__global__ void prep_kn_kernel(const float* __restrict__ key) {
    int row  = blockIdx.x * 8 + (threadIdx.x >> 5);
    int lane = threadIdx.x & 31;
    if (row >= NR) return;
    if (row >= NK) { if (lane == 0) g_kn[row] = __int_as_float(0x7f800000); return; }
    float s = 0.0f;
    for (int d = lane; d < D_; d += 32) {
        float v = key[row * D_ + d];
        s = fmaf(v, v, s);
    }
    #pragma unroll
    for (int off = 16; off > 0; off >>= 1)
        s += __shfl_down_sync(0xffffffffu, s, off);
    if (lane == 0) g_kn[row] = s;
}

__global__ void init_cand_kernel() {
    int t = blockIdx.x * 256 + threadIdx.x;
    if (t < NR) g_cand[t] = 0xFFFFFFFFFFFFFFFFull;
}

// ---------------- main mma.sync GEMM + argmin ----------------
// smem: As buf0 (16KB) | Bs buf0 (16KB) | As buf1 | Bs buf1 | kns (512B)
#define SMEM_TOTAL (65536 + 512)

__global__ __launch_bounds__(256, 2) void nn_mma_kernel() {
    extern __shared__ __align__(128) char smem[];
    float* kns = (float*)(smem + 65536);
    uint32_t sb = smem_u32(smem);

    const int tid = threadIdx.x;
    const int l   = tid & 31;
    const int wid = tid >> 5;
    const int wm  = wid & 3;    // 4 M-warps (32 rows each)
    const int wn  = wid >> 2;   // 2 N-warps (64 cols each)
    const int m0  = blockIdx.x * BM;
    const int n0  = blockIdx.y * BN;

    const float* Ag = g_A + (size_t)m0 * KT;
    const float* Bg = g_B + (size_t)n0 * KT;

    if (tid < BN) kns[tid] = g_kn[n0 + tid];

    // ldmatrix per-lane row/khalf decomposition
    const int a_r  = (l & 7) | (((l >> 3) & 1) << 3);  // m0-7 / m8-15
    const int a_kh = (l >> 4) & 1;                     // k chunk half
    const int b_r  = (l & 7) | (((l >> 4) & 1) << 3);  // n0-7 / n8-15
    const int b_kh = (l >> 3) & 1;

    float acc[2][8][4];
    #pragma unroll
    for (int mi = 0; mi < 2; ++mi)
        #pragma unroll
        for (int ni = 0; ni < 8; ++ni)
            #pragma unroll
            for (int c = 0; c < 4; ++c) acc[mi][ni][c] = 0.0f;

    // issue one k-tile of A+B into buffer buf (swizzled)
    auto issue = [&](int kt, int buf) {
        uint32_t ab = sb + (uint32_t)buf * 32768;
        uint32_t bb = ab + 16384;
        const float* As = Ag + kt * BK;
        const float* Bs = Bg + kt * BK;
        #pragma unroll
        for (int i = tid; i < 1024; i += 256) {
            int r = i >> 3, c = i & 7;
            uint32_t off = ((uint32_t)r << 7) | ((uint32_t)(c ^ (r & 7)) << 4);
            cp16(ab + off, As + (size_t)r * KT + c * 4);
            cp16(bb + off, Bs + (size_t)r * KT + c * 4);
        }
        asm volatile("cp.async.commit_group;" ::: "memory");
    };

    issue(0, 0);

    for (int kt = 0; kt < KTILES; ++kt) {
        if (kt + 1 < KTILES) {
            issue(kt + 1, (kt + 1) & 1);
            asm volatile("cp.async.wait_group 1;" ::: "memory");
        } else {
            asm volatile("cp.async.wait_group 0;" ::: "memory");
        }
        __syncthreads();

        uint32_t ab = sb + (uint32_t)(kt & 1) * 32768;
        uint32_t bb = ab + 16384;

        #pragma unroll
        for (int ks = 0; ks < 4; ++ks) {
            uint32_t a[2][4];
            #pragma unroll
            for (int mi = 0; mi < 2; ++mi) {
                int row = wm * 32 + mi * 16 + a_r;
                uint32_t chunk = (uint32_t)((ks * 2 + a_kh) ^ (row & 7));
                ldmatrix_x4(a[mi], ab + ((uint32_t)row << 7) + (chunk << 4));
            }
            #pragma unroll
            for (int nj = 0; nj < 4; ++nj) {
                uint32_t b4[4];
                int nrow = wn * 64 + nj * 16 + b_r;
                uint32_t chunk = (uint32_t)((ks * 2 + b_kh) ^ (nrow & 7));
                ldmatrix_x4(b4, bb + ((uint32_t)nrow << 7) + (chunk << 4));
                #pragma unroll
                for (int mi = 0; mi < 2; ++mi) {
                    mma_tf32(acc[mi][2 * nj],     a[mi], b4[0], b4[1]);
                    mma_tf32(acc[mi][2 * nj + 1], a[mi], b4[2], b4[3]);
                }
            }
        }
        __syncthreads();   // buffer kt&1 free for next issue
    }

    // ---- argmin epilogue ----
    const int q = l & 3, g = l >> 2;
    float best[4];
    int   bidx[4];
    #pragma unroll
    for (int s = 0; s < 4; ++s) { best[s] = 3.402823466e38f; bidx[s] = 0; }

    #pragma unroll
    for (int mi = 0; mi < 2; ++mi) {
        #pragma unroll
        for (int ni = 0; ni < 8; ++ni) {
            int cb = wn * 64 + ni * 8 + q * 2;
            float kn0 = kns[cb], kn1 = kns[cb + 1];
            int col0 = n0 + cb;
            #pragma unroll
            for (int h = 0; h < 2; ++h) {
                int s = mi * 2 + h;
                float s0 = fmaf(-2.0f, acc[mi][ni][h * 2],     kn0);
                float s1 = fmaf(-2.0f, acc[mi][ni][h * 2 + 1], kn1);
                if (s0 < best[s]) { best[s] = s0; bidx[s] = col0; }
                if (s1 < best[s]) { best[s] = s1; bidx[s] = col0 + 1; }
            }
        }
    }

    #pragma unroll
    for (int s = 0; s < 4; ++s) {
        float b = best[s];
        int   i = bidx[s];
        #pragma unroll
        for (int off = 1; off <= 2; off <<= 1) {
            float ob = __shfl_xor_sync(0xffffffffu, b, off);
            int   oi = __shfl_xor_sync(0xffffffffu, i, off);
            if (ob < b || (ob == b && oi < i)) { b = ob; i = oi; }
        }
        if (q == 0) {
            int row = m0 + wm * 32 + (s >> 1) * 16 + g + (s & 1) * 8;
            if (row < NQ)
                atomicMin(&g_cand[row], (((ull)fkey(b)) << 32) | (unsigned)i);
        }
    }
}

// ---------------- fold ----------------
__global__ void fold_kernel(const float* __restrict__ value, float* __restrict__ out) {
    int pix = blockIdx.x * blockDim.x + threadIdx.x;
    if (pix >= H * H) return;
    int y = pix / H, x = pix - y * H;
    int pi0 = max(0, y - 6), pi1 = min(HO - 1, y);
    int pj0 = max(0, x - 6), pj1 = min(HO - 1, x);
    float s0 = 0.0f, s1 = 0.0f, s2 = 0.0f;
    for (int pi = pi0; pi <= pi1; ++pi) {
        int di = y - pi;
        for (int pj = pj0; pj <= pj1; ++pj) {
            int row  = (int)(unsigned)(g_cand[pi * HO + pj] & 0xffffffffull);
            int base = row * D_ + di * 7 + (x - pj);
            s0 += __ldg(value + base);
            s1 += __ldg(value + base + 49);
            s2 += __ldg(value + base + 98);
        }
    }
    float inv = 1.0f / (float)((pi1 - pi0 + 1) * (pj1 - pj0 + 1));
    out[pix]             = s0 * inv;
    out[H * H + pix]     = s1 * inv;
    out[2 * H * H + pix] = s2 * inv;
}

// ---------------- launch ----------------
extern "C" void kernel_launch(void* const* d_in, const int* in_sizes, int n_in,
                              void* d_out, int out_size) {
    const float* query = (const float*)d_in[0];
    const float* key   = (const float*)d_in[1];
    const float* value = (const float*)d_in[2];
    float* out = (float*)d_out;

    {
        int n = NR * KTERM;                        // 1,310,720
        prep_A_kernel<<<(n + 255) / 256, 256>>>(query);
        prep_B_kernel<<<(n + 255) / 256, 256>>>(key);
        prep_kn_kernel<<<NR / 8, 256>>>(key);
        init_cand_kernel<<<NR / 256, 256>>>();
    }
    {
        cudaFuncSetAttribute(nn_mma_kernel,
                             cudaFuncAttributeMaxDynamicSharedMemorySize, SMEM_TOTAL);
        dim3 grid(NR / BM, NR / BN);               // 64 x 64
        nn_mma_kernel<<<grid, 256, SMEM_TOTAL>>>();
    }
    {
        int n = H * H;
        fold_kernel<<<(n + 127) / 128, 128>>>(value, out);
    }
}

// round 5
// speedup vs baseline: 3.4971x; 1.0152x over previous
#include <cuda_runtime.h>
#include <cstdint>

typedef unsigned long long ull;

// ---------------- problem constants ----------------
#define NQ 8100
#define NK 8100
#define D_ 147
#define HO 90
#define H  96

#define KT    448          // [big(147) | small(147) | big(147) | pad(7)]
#define NR    8192         // padded rows
#define BM    128
#define BN    128
#define BK    32
#define KTILES 14          // 448/32

// ---------------- device scratch ----------------
__device__ __align__(256) float g_A[(size_t)NR * KT];   // [qb | qs | qb]
__device__ __align__(256) float g_B[(size_t)NR * KT];   // [kb | kb | ks]
__device__ float g_kn[NR];
__device__ ull   g_cand[NR];

// ---------------- helpers ----------------
__device__ __forceinline__ uint32_t smem_u32(const void* p) {
    uint32_t a;
    asm("{ .reg .u64 t; cvta.to.shared.u64 t, %1; cvt.u32.u64 %0, t; }" : "=r"(a) : "l"(p));
    return a;
}
__device__ __forceinline__ unsigned fkey(float f) {
    unsigned u = __float_as_uint(f);
    return (u & 0x80000000u) ? ~u : (u | 0x80000000u);
}
__device__ __forceinline__ void cp16(uint32_t dst, const void* src) {
    asm volatile("cp.async.cg.shared.global [%0], [%1], 16;" :: "r"(dst), "l"(src));
}
__device__ __forceinline__ void ldmatrix_x4(uint32_t* r, uint32_t addr) {
    asm volatile("ldmatrix.sync.aligned.m8n8.x4.shared.b16 {%0,%1,%2,%3}, [%4];"
                 : "=r"(r[0]), "=r"(r[1]), "=r"(r[2]), "=r"(r[3]) : "r"(addr));
}
__device__ __forceinline__ void mma_tf32(float* c, const uint32_t* a, uint32_t b0, uint32_t b1) {
    asm volatile(
        "mma.sync.aligned.m16n8k8.row.col.f32.tf32.tf32.f32 "
        "{%0,%1,%2,%3}, {%4,%5,%6,%7}, {%8,%9}, {%0,%1,%2,%3};"
        : "+f"(c[0]), "+f"(c[1]), "+f"(c[2]), "+f"(c[3])
        : "r"(a[0]), "r"(a[1]), "r"(a[2]), "r"(a[3]), "r"(b0), "r"(b1));
}
__device__ __forceinline__ float tf32_rna(float x) {
    uint32_t u; asm("cvt.rna.tf32.f32 %0, %1;" : "=r"(u) : "f"(x));
    return __uint_as_float(u);
}

// ---------------- prep kernels ----------------
// A row layout: [qb(0..146) | qs(0..146) | qb(0..146) | 0 x7]
__global__ void prep_A_kernel(const float* __restrict__ query) {
    int t = blockIdx.x * 256 + threadIdx.x;
    if (t >= NR * KT) return;
    int p = t / KT, k = t - p * KT;
    int term = 0, kk = k;
    if (k >= 294)      { term = 2; kk = k - 294; }
    else if (k >= 147) { term = 1; kk = k - 147; }
    float v = 0.0f;
    if (p < NQ && kk < D_ && k < 441) {
        int c  = kk / 49;
        int rr = kk - c * 49;
        int i  = rr / 7;
        int j  = rr - i * 7;
        int pi = p / HO;
        int pj = p - pi * HO;
        float x = query[c * (H * H) + (pi + i) * H + (pj + j)];
        float big = tf32_rna(x);
        v = (term == 1) ? tf32_rna(x - big) : big;
    }
    g_A[t] = v;
}

// B row layout: [kb | kb | ks | 0 x7]
__global__ void prep_B_kernel(const float* __restrict__ key) {
    int t = blockIdx.x * 256 + threadIdx.x;
    if (t >= NR * KT) return;
    int p = t / KT, k = t - p * KT;
    int term = 0, kk = k;
    if (k >= 294)      { term = 2; kk = k - 294; }
    else if (k >= 147) { term = 1; kk = k - 147; }
    float v = 0.0f;
    if (p < NK && k < 441) {
        float x = key[p * D_ + kk];
        float big = tf32_rna(x);
        v = (term == 2) ? tf32_rna(x - big) : big;
    }
    g_B[t] = v;
}

__global__ void prep_kn_kernel(const float* __restrict__ key) {
    int row  = blockIdx.x * 8 + (threadIdx.x >> 5);
    int lane = threadIdx.x & 31;
    if (row >= NR) return;
    if (lane == 0) g_cand[row] = 0xFFFFFFFFFFFFFFFFull;
    if (row >= NK) { if (lane == 0) g_kn[row] = __int_as_float(0x7f800000); return; }
    float s = 0.0f;
    for (int d = lane; d < D_; d += 32) {
        float v = key[row * D_ + d];
        s = fmaf(v, v, s);
    }
    #pragma unroll
    for (int off = 16; off > 0; off >>= 1)
        s += __shfl_down_sync(0xffffffffu, s, off);
    if (lane == 0) g_kn[row] = s;
}

// ---------------- main mma.sync GEMM + argmin ----------------
// smem: 3 x (As 16KB | Bs 16KB) | kns (512B)
#define BUF_BYTES 32768
#define SMEM_TOTAL (3 * BUF_BYTES + 512)

__global__ __launch_bounds__(256, 2) void nn_mma_kernel() {
    extern __shared__ __align__(128) char smem[];
    float* kns = (float*)(smem + 3 * BUF_BYTES);
    uint32_t sb = smem_u32(smem);

    const int tid = threadIdx.x;
    const int l   = tid & 31;
    const int wid = tid >> 5;
    const int wm  = wid & 3;    // 4 M-warps (32 rows each)
    const int wn  = wid >> 2;   // 2 N-warps (64 cols each)
    const int m0  = blockIdx.x * BM;
    const int n0  = blockIdx.y * BN;

    const float* Ag = g_A + (size_t)m0 * KT;
    const float* Bg = g_B + (size_t)n0 * KT;

    if (tid < BN) kns[tid] = g_kn[n0 + tid];

    const int a_r  = (l & 7) | (((l >> 3) & 1) << 3);
    const int a_kh = (l >> 4) & 1;
    const int b_r  = (l & 7) | (((l >> 4) & 1) << 3);
    const int b_kh = (l >> 3) & 1;

    float acc[2][8][4];
    #pragma unroll
    for (int mi = 0; mi < 2; ++mi)
        #pragma unroll
        for (int ni = 0; ni < 8; ++ni)
            #pragma unroll
            for (int c = 0; c < 4; ++c) acc[mi][ni][c] = 0.0f;

    auto issue = [&](int kt) {
        uint32_t ab = sb + (uint32_t)(kt % 3) * BUF_BYTES;
        uint32_t bb = ab + 16384;
        const float* As = Ag + kt * BK;
        const float* Bs = Bg + kt * BK;
        #pragma unroll
        for (int i = tid; i < 1024; i += 256) {
            int r = i >> 3, c = i & 7;
            uint32_t off = ((uint32_t)r << 7) | ((uint32_t)(c ^ (r & 7)) << 4);
            cp16(ab + off, As + (size_t)r * KT + c * 4);
            cp16(bb + off, Bs + (size_t)r * KT + c * 4);
        }
        asm volatile("cp.async.commit_group;" ::: "memory");
    };

    issue(0);
    issue(1);

    for (int kt = 0; kt < KTILES; ++kt) {
        if (kt + 2 < KTILES) {
            issue(kt + 2);
            asm volatile("cp.async.wait_group 2;" ::: "memory");
        } else if (kt + 1 < KTILES) {
            asm volatile("cp.async.wait_group 1;" ::: "memory");
        } else {
            asm volatile("cp.async.wait_group 0;" ::: "memory");
        }
        __syncthreads();

        uint32_t ab = sb + (uint32_t)(kt % 3) * BUF_BYTES;
        uint32_t bb = ab + 16384;

        #pragma unroll
        for (int ks = 0; ks < 4; ++ks) {
            uint32_t a[2][4];
            #pragma unroll
            for (int mi = 0; mi < 2; ++mi) {
                int row = wm * 32 + mi * 16 + a_r;
                uint32_t chunk = (uint32_t)((ks * 2 + a_kh) ^ (row & 7));
                ldmatrix_x4(a[mi], ab + ((uint32_t)row << 7) + (chunk << 4));
            }
            #pragma unroll
            for (int nj = 0; nj < 4; ++nj) {
                uint32_t b4[4];
                int nrow = wn * 64 + nj * 16 + b_r;
                uint32_t chunk = (uint32_t)((ks * 2 + b_kh) ^ (nrow & 7));
                ldmatrix_x4(b4, bb + ((uint32_t)nrow << 7) + (chunk << 4));
                #pragma unroll
                for (int mi = 0; mi < 2; ++mi) {
                    mma_tf32(acc[mi][2 * nj],     a[mi], b4[0], b4[1]);
                    mma_tf32(acc[mi][2 * nj + 1], a[mi], b4[2], b4[3]);
                }
            }
        }
        __syncthreads();   // buffer kt%3 free for re-issue at kt+3
    }

    // ---- argmin epilogue ----
    const int q = l & 3, g = l >> 2;
    float best[4];
    int   bidx[4];
    #pragma unroll
    for (int s = 0; s < 4; ++s) { best[s] = 3.402823466e38f; bidx[s] = 0; }

    #pragma unroll
    for (int mi = 0; mi < 2; ++mi) {
        #pragma unroll
        for (int ni = 0; ni < 8; ++ni) {
            int cb = wn * 64 + ni * 8 + q * 2;
            float kn0 = kns[cb], kn1 = kns[cb + 1];
            int col0 = n0 + cb;
            #pragma unroll
            for (int h = 0; h < 2; ++h) {
                int s = mi * 2 + h;
                float s0 = fmaf(-2.0f, acc[mi][ni][h * 2],     kn0);
                float s1 = fmaf(-2.0f, acc[mi][ni][h * 2 + 1], kn1);
                if (s0 < best[s]) { best[s] = s0; bidx[s] = col0; }
                if (s1 < best[s]) { best[s] = s1; bidx[s] = col0 + 1; }
            }
        }
    }

    #pragma unroll
    for (int s = 0; s < 4; ++s) {
        float b = best[s];
        int   i = bidx[s];
        #pragma unroll
        for (int off = 1; off <= 2; off <<= 1) {
            float ob = __shfl_xor_sync(0xffffffffu, b, off);
            int   oi = __shfl_xor_sync(0xffffffffu, i, off);
            if (ob < b || (ob == b && oi < i)) { b = ob; i = oi; }
        }
        if (q == 0) {
            int row = m0 + wm * 32 + (s >> 1) * 16 + g + (s & 1) * 8;
            if (row < NQ)
                atomicMin(&g_cand[row], (((ull)fkey(b)) << 32) | (unsigned)i);
        }
    }
}

// ---------------- fold ----------------
__global__ void fold_kernel(const float* __restrict__ value, float* __restrict__ out) {
    int pix = blockIdx.x * blockDim.x + threadIdx.x;
    if (pix >= H * H) return;
    int y = pix / H, x = pix - y * H;
    int pi0 = max(0, y - 6), pi1 = min(HO - 1, y);
    int pj0 = max(0, x - 6), pj1 = min(HO - 1, x);
    float s0 = 0.0f, s1 = 0.0f, s2 = 0.0f;
    for (int pi = pi0; pi <= pi1; ++pi) {
        int di = y - pi;
        for (int pj = pj0; pj <= pj1; ++pj) {
            int row  = (int)(unsigned)(g_cand[pi * HO + pj] & 0xffffffffull);
            int base = row * D_ + di * 7 + (x - pj);
            s0 += __ldg(value + base);
            s1 += __ldg(value + base + 49);
            s2 += __ldg(value + base + 98);
        }
    }
    float inv = 1.0f / (float)((pi1 - pi0 + 1) * (pj1 - pj0 + 1));
    out[pix]             = s0 * inv;
    out[H * H + pix]     = s1 * inv;
    out[2 * H * H + pix] = s2 * inv;
}

// ---------------- launch ----------------
extern "C" void kernel_launch(void* const* d_in, const int* in_sizes, int n_in,
                              void* d_out, int out_size) {
    const float* query = (const float*)d_in[0];
    const float* key   = (const float*)d_in[1];
    const float* value = (const float*)d_in[2];
    float* out = (float*)d_out;

    {
        int n = NR * KT;                           // 3,670,016
        prep_A_kernel<<<(n + 255) / 256, 256>>>(query);
        prep_B_kernel<<<(n + 255) / 256, 256>>>(key);
        prep_kn_kernel<<<NR / 8, 256>>>(key);
    }
    {
        cudaFuncSetAttribute(nn_mma_kernel,
                             cudaFuncAttributeMaxDynamicSharedMemorySize, SMEM_TOTAL);
        dim3 grid(NR / BM, NR / BN);               // 64 x 64
        nn_mma_kernel<<<grid, 256, SMEM_TOTAL>>>();
    }
    {
        int n = H * H;
        fold_kernel<<<(n + 127) / 128, 128>>>(value, out);
    }
}